// round 6
// baseline (speedup 1.0000x reference)
#include <cuda_runtime.h>
#include <math.h>

// Problem constants
#define B    64
#define SEQ  512
#define H    1024
#define OUTD 128

// Fused kernel config
#define GR   128           // recurrence CTAs (own 8 columns of W_hh each)
#define NEP  20            // epilogue worker CTAs (fill remaining SMs)
#define GT   (GR + NEP)    // 148 = SM count -> all co-resident, 1 CTA/SM
#define CPC  8             // columns per recurrence CTA (H / GR)
#define NT   256
#define NW   8             // warps per CTA
#define KC   (H / NW)      // 128 k per warp (64 k-pairs via lane k-parity)
#define NSLOT (2 * NW)     // 16 partial slots
#define SLOTSTRIDE 577     // 64*9 + 1 pad

static_assert(GR * CPC == H, "partition");

typedef unsigned long long u64;

// Scratch (device globals: allocation-free rule).
__device__ float g_hs[(size_t)SEQ * H * B];  // hidden states [t][h][b]
__device__ float g_h0[H * B];                // initial h = 0 (never written)
__device__ unsigned g_flag[GR];              // per-CTA steps-completed counters

// ---------------------------------------------------------------------------
// Acquire/release flag ops (L2-coherent; bypass non-coherent L1)
// ---------------------------------------------------------------------------
__device__ __forceinline__ unsigned ld_acq(const unsigned* p) {
    unsigned v;
    asm volatile("ld.acquire.gpu.global.u32 %0, [%1];" : "=r"(v) : "l"(p) : "memory");
    return v;
}
__device__ __forceinline__ void st_rel(unsigned* p, unsigned v) {
    asm volatile("st.release.gpu.global.u32 [%0], %1;" :: "l"(p), "r"(v) : "memory");
}

// ---------------------------------------------------------------------------
// Packed f32x2 helpers (Blackwell FFMA2)
// ---------------------------------------------------------------------------
__device__ __forceinline__ u64 dup2(float x) {
    u64 r; unsigned u = __float_as_uint(x);
    asm("mov.b64 %0, {%1, %2};" : "=l"(r) : "r"(u), "r"(u));
    return r;
}
__device__ __forceinline__ void ffma2(u64& d, u64 a, u64 b) {
    asm("fma.rn.f32x2 %0, %1, %2, %3;" : "=l"(d) : "l"(a), "l"(b), "l"(d));
}
__device__ __forceinline__ void unpack2(u64 v, float& x, float& y) {
    unsigned lo, hi;
    asm("mov.b64 {%0, %1}, %2;" : "=r"(lo), "=r"(hi) : "l"(v));
    x = __uint_as_float(lo); y = __uint_as_float(hi);
}

__device__ __forceinline__ float tanh_safe(float x) {
    float ax = fabsf(x);
    float e  = __expf(2.0f * ax);
    float r  = 1.0f - 2.0f / (e + 1.0f);
    return copysignf(r, x);
}

// ---------------------------------------------------------------------------
// Reset flags each launch (stream-ordered before the fused kernel) so graph
// replays see flag[p]=0 at start. Deterministic.
// ---------------------------------------------------------------------------
__global__ void rnn_reset_kernel() {
    if (threadIdx.x < GR) g_flag[threadIdx.x] = 0u;
}

// ---------------------------------------------------------------------------
// Fused persistent kernel.
//   bid <  GR : recurrence role. h_t = tanh(h_{t-1} @ W_hh + W_xh[X[:,t]] + b_h)
//               CTA owns columns [bid*8, bid*8+8); W slice resident in smem.
//               Warp w's k-range [128w,128w+128) depends only on producer CTAs
//               [16w,16w+16) -> fine-grained flag wait, no global barrier.
//   bid >= GR : epilogue worker. For t = bid-GR, t+NEP, ... : wait for all 128
//               flags >= t+1, then out[:,t,:] = hs[t] @ W_hy + b_y.
// All spin loops use __nanosleep backoff to keep flag polling off the L2
// critical path (the h broadcast needs that bandwidth).
// ---------------------------------------------------------------------------
__global__ void __launch_bounds__(NT, 1)
rnn_fused_kernel(const int* __restrict__ X,
                 const float* __restrict__ W_hh,
                 const float* __restrict__ W_xh,
                 const float* __restrict__ W_hy,
                 const float* __restrict__ b_h,
                 const float* __restrict__ b_y,
                 float* __restrict__ out) {
    extern __shared__ float sm[];
    const int tid = threadIdx.x;
    const int bid = blockIdx.x;

    if (bid < GR) {
        // ================= recurrence role =================
        float* ws  = sm;                              // [H][CPC]   32 KB
        float* red = sm + H * CPC;                    // [16][577]  ~36 KB
        int*   tok = (int*)(red + NSLOT * SLOTSTRIDE);

        const int c0 = bid * CPC;

        for (int i = tid; i < H * CPC; i += NT) {
            int k = i >> 3, j = i & 7;
            ws[i] = W_hh[(size_t)k * H + c0 + j];
        }

        const int w    = tid >> 5;
        const int lane = tid & 31;
        const int b4   = lane & 15;
        const int kpar = lane >> 4;
        const int bb0  = b4 * 4;
        const int slot = w * 2 + kpar;
        float* rstore  = red + slot * SLOTSTRIDE + bb0 * 9;

        // This warp's producer set (16 flags, duplicated across half-warps)
        const unsigned* myflag = &g_flag[(w << 4) | (lane & 15)];

        const int jr0 = tid >> 6;     // 0..3
        const int br  = tid & 63;
        const float bh0 = b_h[c0 + jr0];
        const float bh1 = b_h[c0 + jr0 + 4];

        __syncthreads();

        for (int t = 0; t < SEQ; t++) {
            const float* hp = t ? (g_hs + (size_t)(t - 1) * H * B) : g_h0;
            if (tid < B) tok[tid] = X[tid * SEQ + t];

            // Wait until this warp's 16 producers published h_{t-1}.
            if (t) {
                const unsigned tgt = (unsigned)t;
                while (true) {
                    unsigned f = ld_acq(myflag);
                    if (__all_sync(0xFFFFFFFFu, f >= tgt)) break;
                    __nanosleep(64);
                }
            }

            u64 acc[4][4];
            #pragma unroll
            for (int bi = 0; bi < 4; bi++)
                #pragma unroll
                for (int jp = 0; jp < 4; jp++) acc[bi][jp] = 0ull;

            const float* hb = hp + (size_t)(w * KC + kpar) * B + bb0;
            const float* wb = ws + (w * KC + kpar) * CPC;

            #pragma unroll 8
            for (int it = 0; it < KC / 2; it++) {
                float4 hv = *(const float4*)(hb + (size_t)it * 2 * B);
                ulonglong2 w0 = *(const ulonglong2*)(wb + it * 2 * CPC);
                ulonglong2 w1 = *(const ulonglong2*)(wb + it * 2 * CPC + 4);
                u64 h0 = dup2(hv.x), h1 = dup2(hv.y), h2 = dup2(hv.z), h3 = dup2(hv.w);
                ffma2(acc[0][0], h0, w0.x); ffma2(acc[0][1], h0, w0.y);
                ffma2(acc[0][2], h0, w1.x); ffma2(acc[0][3], h0, w1.y);
                ffma2(acc[1][0], h1, w0.x); ffma2(acc[1][1], h1, w0.y);
                ffma2(acc[1][2], h1, w1.x); ffma2(acc[1][3], h1, w1.y);
                ffma2(acc[2][0], h2, w0.x); ffma2(acc[2][1], h2, w0.y);
                ffma2(acc[2][2], h2, w1.x); ffma2(acc[2][3], h2, w1.y);
                ffma2(acc[3][0], h3, w0.x); ffma2(acc[3][1], h3, w0.y);
                ffma2(acc[3][2], h3, w1.x); ffma2(acc[3][3], h3, w1.y);
            }

            #pragma unroll
            for (int bi = 0; bi < 4; bi++) {
                float f[8];
                unpack2(acc[bi][0], f[0], f[1]);
                unpack2(acc[bi][1], f[2], f[3]);
                unpack2(acc[bi][2], f[4], f[5]);
                unpack2(acc[bi][3], f[6], f[7]);
                #pragma unroll
                for (int j = 0; j < 8; j++) rstore[bi * 9 + j] = f[j];
            }
            __syncthreads();

            // Reduce 16 slots + input proj + bias + tanh; write h_t [h][b].
            {
                float s0 = 0.f, s1 = 0.f;
                #pragma unroll
                for (int sl = 0; sl < NSLOT; sl++) {
                    const float* rb = red + sl * SLOTSTRIDE + br * 9;
                    s0 += rb[jr0];
                    s1 += rb[jr0 + 4];
                }
                int tk = tok[br];
                const float* wx = W_xh + (size_t)tk * H + c0;
                float x0 = s0 + wx[jr0]     + bh0;
                float x1 = s1 + wx[jr0 + 4] + bh1;
                float* ho = g_hs + (size_t)t * H * B;
                ho[(size_t)(c0 + jr0)     * B + br] = tanh_safe(x0);
                ho[(size_t)(c0 + jr0 + 4) * B + br] = tanh_safe(x1);
            }
            __syncthreads();   // all writes done before publishing

            if (tid == 0) st_rel(&g_flag[bid], (unsigned)(t + 1));
        }
    } else {
        // ================= epilogue worker role =================
        float* hc = sm;             // [k64][b64]  16 KB
        float* Wc = sm + 64 * 64;   // [k64][o128] 32 KB

        const int b0 = (tid & 15) * 4;
        const int o0 = (tid >> 4) * 8;
        const int pb = (tid & 31) * 4;   // 4 flags per lane covers all 128

        float byv[8];
        #pragma unroll
        for (int oi = 0; oi < 8; oi++) byv[oi] = b_y[o0 + oi];

        for (int t = bid - GR; t < SEQ; t += NEP) {
            // Wait until ALL producers finished step t.
            {
                const unsigned tgt = (unsigned)(t + 1);
                while (true) {
                    unsigned f0 = ld_acq(&g_flag[pb]);
                    unsigned f1 = ld_acq(&g_flag[pb + 1]);
                    unsigned f2 = ld_acq(&g_flag[pb + 2]);
                    unsigned f3 = ld_acq(&g_flag[pb + 3]);
                    unsigned mn = min(min(f0, f1), min(f2, f3));
                    if (__all_sync(0xFFFFFFFFu, mn >= tgt)) break;
                    __nanosleep(256);
                }
            }

            u64 acc[4][4];
            #pragma unroll
            for (int bi = 0; bi < 4; bi++)
                #pragma unroll
                for (int op = 0; op < 4; op++) acc[bi][op] = 0ull;

            const float* hsrc = g_hs + (size_t)t * H * B;

            for (int k0 = 0; k0 < H; k0 += 64) {
                const float4* hsv = (const float4*)(hsrc + (size_t)k0 * B);
                float4* hcv = (float4*)hc;
                #pragma unroll
                for (int i = 0; i < 4; i++) hcv[tid + i * 256] = hsv[tid + i * 256];

                const float4* wsv = (const float4*)(W_hy + (size_t)k0 * OUTD);
                float4* wcv = (float4*)Wc;
                #pragma unroll
                for (int i = 0; i < 8; i++) wcv[tid + i * 256] = wsv[tid + i * 256];

                __syncthreads();

                #pragma unroll 4
                for (int k = 0; k < 64; k++) {
                    float4 hv = *(const float4*)(hc + k * 64 + b0);
                    ulonglong2 wq0 = *(const ulonglong2*)(Wc + k * OUTD + o0);
                    ulonglong2 wq1 = *(const ulonglong2*)(Wc + k * OUTD + o0 + 4);
                    u64 h0 = dup2(hv.x), h1 = dup2(hv.y), h2 = dup2(hv.z), h3 = dup2(hv.w);
                    ffma2(acc[0][0], h0, wq0.x); ffma2(acc[0][1], h0, wq0.y);
                    ffma2(acc[0][2], h0, wq1.x); ffma2(acc[0][3], h0, wq1.y);
                    ffma2(acc[1][0], h1, wq0.x); ffma2(acc[1][1], h1, wq0.y);
                    ffma2(acc[1][2], h1, wq1.x); ffma2(acc[1][3], h1, wq1.y);
                    ffma2(acc[2][0], h2, wq0.x); ffma2(acc[2][1], h2, wq0.y);
                    ffma2(acc[2][2], h2, wq1.x); ffma2(acc[2][3], h2, wq1.y);
                    ffma2(acc[3][0], h3, wq0.x); ffma2(acc[3][1], h3, wq0.y);
                    ffma2(acc[3][2], h3, wq1.x); ffma2(acc[3][3], h3, wq1.y);
                }
                __syncthreads();
            }

            #pragma unroll
            for (int bi = 0; bi < 4; bi++) {
                float f[8];
                unpack2(acc[bi][0], f[0], f[1]);
                unpack2(acc[bi][1], f[2], f[3]);
                unpack2(acc[bi][2], f[4], f[5]);
                unpack2(acc[bi][3], f[6], f[7]);
                float* dst = out + ((size_t)(b0 + bi) * SEQ + t) * OUTD + o0;
                float4 v0, v1;
                v0.x = f[0] + byv[0]; v0.y = f[1] + byv[1];
                v0.z = f[2] + byv[2]; v0.w = f[3] + byv[3];
                v1.x = f[4] + byv[4]; v1.y = f[5] + byv[5];
                v1.z = f[6] + byv[6]; v1.w = f[7] + byv[7];
                *(float4*)(dst)     = v0;
                *(float4*)(dst + 4) = v1;
            }
        }
    }
}

// ---------------------------------------------------------------------------
// Launch. Inputs: X[i32 64x512], W_hh[f32 1024x1024], W_xh[f32 128x1024],
// W_hy[f32 1024x128], b_h[1024], b_y[128]. Output: f32 [64][512][128].
// ---------------------------------------------------------------------------
extern "C" void kernel_launch(void* const* d_in, const int* in_sizes, int n_in,
                              void* d_out, int out_size) {
    const int*   X    = (const int*)  d_in[0];
    const float* W_hh = (const float*)d_in[1];
    const float* W_xh = (const float*)d_in[2];
    const float* W_hy = (const float*)d_in[3];
    const float* b_h  = (const float*)d_in[4];
    const float* b_y  = (const float*)d_in[5];
    float* out = (float*)d_out;

    const int smem_rec = (H * CPC + NSLOT * SLOTSTRIDE) * (int)sizeof(float)
                       + B * (int)sizeof(int);
    const int smem_epi = (64 * 64 + 64 * OUTD) * (int)sizeof(float);
    const int smem = smem_rec > smem_epi ? smem_rec : smem_epi;

    cudaFuncSetAttribute(rnn_fused_kernel,
                         cudaFuncAttributeMaxDynamicSharedMemorySize, smem);

    rnn_reset_kernel<<<1, 128>>>();
    rnn_fused_kernel<<<GT, NT, smem>>>(X, W_hh, W_xh, W_hy, b_h, b_y, out);
}

// round 7
// speedup vs baseline: 1.2762x; 1.2762x over previous
#include <cuda_runtime.h>
#include <math.h>

// Problem constants
#define B    64
#define SEQ  512
#define H    1024
#define OUTD 128

// Recurrence partition: 4 independent batch-groups x 32 column-group CTAs.
#define NBG  4             // batch groups (independent recurrence chains)
#define NCG  32            // CTAs per batch group (column split)
#define G    (NBG * NCG)   // 128 CTAs, co-resident (<= 148 SMs), 1 CTA/SM
#define CPC  32            // columns of W_hh per CTA (H / NCG)
#define BPC  16            // batches per CTA (B / NBG)
#define NT   256
#define NW   8             // warps per CTA
#define KC   (H / NW)      // 128 k per warp (lane k-parity -> 64 iters/lane)
#define NSLOT (2 * NW)     // 16 partial slots (warp x k-parity)
#define ROWS  36           // padded row stride for partials [b][j]: 32 j + pad
#define SLOT  (BPC * ROWS) // 576 floats per slot

static_assert(NCG * CPC == H, "col partition");
static_assert(NBG * BPC == B, "batch partition");

typedef unsigned long long u64;

// Scratch (device globals: allocation-free rule).
__device__ float g_hs[(size_t)SEQ * H * B];  // hidden states [t][h][b]
__device__ float g_h0[H * B];                // initial h = 0 (never written)
__device__ unsigned g_arrive[NBG * 32];      // per-group arrival ctr (spaced 128B)
__device__ volatile unsigned g_release[NBG * 32];

// ---------------------------------------------------------------------------
// Packed f32x2 helpers (Blackwell FFMA2)
// ---------------------------------------------------------------------------
__device__ __forceinline__ u64 dup2(float x) {
    u64 r; unsigned u = __float_as_uint(x);
    asm("mov.b64 %0, {%1, %2};" : "=l"(r) : "r"(u), "r"(u));
    return r;
}
__device__ __forceinline__ void ffma2(u64& d, u64 a, u64 b) {
    asm("fma.rn.f32x2 %0, %1, %2, %3;" : "=l"(d) : "l"(a), "l"(b), "l"(d));
}
__device__ __forceinline__ void unpack2(u64 v, float& x, float& y) {
    unsigned lo, hi;
    asm("mov.b64 {%0, %1}, %2;" : "=r"(lo), "=r"(hi) : "l"(v));
    x = __uint_as_float(lo); y = __uint_as_float(hi);
}

__device__ __forceinline__ float tanh_safe(float x) {
    float ax = fabsf(x);
    float e  = __expf(2.0f * ax);
    float r  = 1.0f - 2.0f / (e + 1.0f);
    return copysignf(r, x);
}

// ---------------------------------------------------------------------------
// Per-batch-group barrier (32 CTAs). Valid: all 128 CTAs co-resident.
// Self-restoring across graph replays (arrive->0, release monotonic).
// ---------------------------------------------------------------------------
__device__ __forceinline__ void group_sync(int gslot) {
    __syncthreads();
    if (threadIdx.x == 0) {
        __threadfence();
        unsigned gen = g_release[gslot];
        if (atomicAdd(&g_arrive[gslot], 1u) == NCG - 1u) {
            g_arrive[gslot] = 0;
            __threadfence();
            g_release[gslot] = gen + 1u;
        } else {
            while (g_release[gslot] == gen) { }
        }
        __threadfence();
    }
    __syncthreads();
}

// ---------------------------------------------------------------------------
// Persistent recurrence: h_t = tanh(h_{t-1} @ W_hh + W_xh[X[:,t]] + b_h)
// CTA (bc, jc): batch rows [bc*16, bc*16+16), W_hh columns [jc*32, jc*32+32).
// W slice (128 KB) resident in smem all 512 steps; per step the CTA reads only
// h[1024][16 batches] = 64 KB (8 MB/step chip-wide, 4x less than full bcast).
// The 4 batch groups are fully independent -> barrier spans 32 CTAs only.
// ---------------------------------------------------------------------------
__global__ void __launch_bounds__(NT, 1)
rnn_recurrence_kernel(const int* __restrict__ X,
                      const float* __restrict__ W_hh,
                      const float* __restrict__ W_xh,
                      const float* __restrict__ b_h) {
    extern __shared__ float sm[];
    float* ws  = sm;                          // [H][CPC]   128 KB
    float* red = sm + H * CPC;                // [16][576]   36 KB
    int*   tok = (int*)(red + NSLOT * SLOT);  // [BPC]

    const int tid = threadIdx.x;
    const int bc  = blockIdx.x >> 5;          // batch group 0..3
    const int jc  = blockIdx.x & 31;          // column group 0..31
    const int c0  = jc * CPC;
    const int b0  = bc * BPC;
    const int gslot = bc * 32;

    // One-time W_hh slice load: ws[k][j], j in [c0, c0+32)
    for (int i = tid; i < H * CPC; i += NT) {
        int k = i >> 5, j = i & 31;
        ws[i] = W_hh[(size_t)k * H + c0 + j];
    }

    const int w    = tid >> 5;
    const int lane = tid & 31;
    const int kpar = lane >> 4;        // k parity
    const int half = lane & 15;
    const int b4   = half & 3;         // batch subgroup (4 batches)
    const int jgrp = half >> 2;        // 8-column subgroup (0..3)
    const int bb0  = b4 * 4;
    const int j0   = jgrp * 8;
    const int slot = w * 2 + kpar;
    u64* rstore = (u64*)(red + slot * SLOT + bb0 * ROWS + j0);

    // Reduction mapping: thread -> (j = tid>>4, b = tid&15), 2 outputs (j, j+16)
    const int jr = tid >> 4;           // 0..15
    const int br = tid & 15;
    const float bh0 = b_h[c0 + jr];
    const float bh1 = b_h[c0 + jr + 16];

    __syncthreads();

    for (int t = 0; t < SEQ; t++) {
        const float* hp = t ? (g_hs + (size_t)(t - 1) * H * B) : g_h0;
        if (tid < BPC) tok[tid] = X[(b0 + tid) * SEQ + t];

        u64 acc[4][4];
        #pragma unroll
        for (int bi = 0; bi < 4; bi++)
            #pragma unroll
            for (int jp = 0; jp < 4; jp++) acc[bi][jp] = 0ull;

        const int kbeg = w * KC + kpar;
        const float* hb = hp + (size_t)kbeg * B + b0 + bb0;
        const float* wb = ws + kbeg * CPC + j0;

        #pragma unroll 8
        for (int it = 0; it < KC / 2; it++) {
            float4 hv = *(const float4*)(hb + (size_t)it * 2 * B);
            ulonglong2 w0 = *(const ulonglong2*)(wb + it * 2 * CPC);      // j0..j0+3
            ulonglong2 w1 = *(const ulonglong2*)(wb + it * 2 * CPC + 4);  // j0+4..j0+7
            u64 h0 = dup2(hv.x), h1 = dup2(hv.y), h2 = dup2(hv.z), h3 = dup2(hv.w);
            ffma2(acc[0][0], h0, w0.x); ffma2(acc[0][1], h0, w0.y);
            ffma2(acc[0][2], h0, w1.x); ffma2(acc[0][3], h0, w1.y);
            ffma2(acc[1][0], h1, w0.x); ffma2(acc[1][1], h1, w0.y);
            ffma2(acc[1][2], h1, w1.x); ffma2(acc[1][3], h1, w1.y);
            ffma2(acc[2][0], h2, w0.x); ffma2(acc[2][1], h2, w0.y);
            ffma2(acc[2][2], h2, w1.x); ffma2(acc[2][3], h2, w1.y);
            ffma2(acc[3][0], h3, w0.x); ffma2(acc[3][1], h3, w0.y);
            ffma2(acc[3][2], h3, w1.x); ffma2(acc[3][3], h3, w1.y);
        }

        // Stash partials: red[slot][b][j], row stride 36 (u64 stores, 8B aligned)
        #pragma unroll
        for (int bi = 0; bi < 4; bi++) {
            u64* rb = (u64*)((float*)rstore + bi * ROWS);
            rb[0] = acc[bi][0]; rb[1] = acc[bi][1];
            rb[2] = acc[bi][2]; rb[3] = acc[bi][3];
        }
        __syncthreads();

        // Reduce 16 slots + input proj + bias + tanh; write h_t [h][b].
        {
            float s0 = 0.f, s1 = 0.f;
            const float* rb = red + br * ROWS + jr;
            #pragma unroll
            for (int sl = 0; sl < NSLOT; sl++) {
                s0 += rb[sl * SLOT];
                s1 += rb[sl * SLOT + 16];
            }
            int tk = tok[br];
            const float* wx = W_xh + (size_t)tk * H + c0;
            float x0 = s0 + wx[jr]      + bh0;
            float x1 = s1 + wx[jr + 16] + bh1;
            float* ho = g_hs + (size_t)t * H * B + b0;
            ho[(size_t)(c0 + jr)      * B + br] = tanh_safe(x0);
            ho[(size_t)(c0 + jr + 16) * B + br] = tanh_safe(x1);
        }

        group_sync(gslot);
    }
}

// ---------------------------------------------------------------------------
// Output projection (separate kernel, R4-proven):
//   out[b][t][o] = sum_h hs[t][h][b] * W_hy[h][o] + b_y[o]
// ---------------------------------------------------------------------------
__global__ void __launch_bounds__(256)
rnn_output_kernel(const float* __restrict__ W_hy,
                  const float* __restrict__ b_y,
                  float* __restrict__ out) {
    __shared__ float hc[64 * 64];    // [k][b]  16 KB
    __shared__ float Wc[64 * OUTD];  // [k][o]  32 KB

    const int t   = blockIdx.x;
    const int tid = threadIdx.x;
    const int b0  = (tid & 15) * 4;
    const int o0  = (tid >> 4) * 8;

    u64 acc[4][4];
    #pragma unroll
    for (int bi = 0; bi < 4; bi++)
        #pragma unroll
        for (int op = 0; op < 4; op++) acc[bi][op] = 0ull;

    const float* hsrc = g_hs + (size_t)t * H * B;

    for (int k0 = 0; k0 < H; k0 += 64) {
        const float4* hsv = (const float4*)(hsrc + (size_t)k0 * B);
        float4* hcv = (float4*)hc;
        #pragma unroll
        for (int i = 0; i < 4; i++) hcv[tid + i * 256] = hsv[tid + i * 256];

        const float4* wsv = (const float4*)(W_hy + (size_t)k0 * OUTD);
        float4* wcv = (float4*)Wc;
        #pragma unroll
        for (int i = 0; i < 8; i++) wcv[tid + i * 256] = wsv[tid + i * 256];

        __syncthreads();

        #pragma unroll 4
        for (int k = 0; k < 64; k++) {
            float4 hv = *(const float4*)(hc + k * 64 + b0);
            ulonglong2 wq0 = *(const ulonglong2*)(Wc + k * OUTD + o0);
            ulonglong2 wq1 = *(const ulonglong2*)(Wc + k * OUTD + o0 + 4);
            u64 h0 = dup2(hv.x), h1 = dup2(hv.y), h2 = dup2(hv.z), h3 = dup2(hv.w);
            ffma2(acc[0][0], h0, wq0.x); ffma2(acc[0][1], h0, wq0.y);
            ffma2(acc[0][2], h0, wq1.x); ffma2(acc[0][3], h0, wq1.y);
            ffma2(acc[1][0], h1, wq0.x); ffma2(acc[1][1], h1, wq0.y);
            ffma2(acc[1][2], h1, wq1.x); ffma2(acc[1][3], h1, wq1.y);
            ffma2(acc[2][0], h2, wq0.x); ffma2(acc[2][1], h2, wq0.y);
            ffma2(acc[2][2], h2, wq1.x); ffma2(acc[2][3], h2, wq1.y);
            ffma2(acc[3][0], h3, wq0.x); ffma2(acc[3][1], h3, wq0.y);
            ffma2(acc[3][2], h3, wq1.x); ffma2(acc[3][3], h3, wq1.y);
        }
        __syncthreads();
    }

    float byv[8];
    #pragma unroll
    for (int oi = 0; oi < 8; oi++) byv[oi] = b_y[o0 + oi];

    #pragma unroll
    for (int bi = 0; bi < 4; bi++) {
        float f[8];
        unpack2(acc[bi][0], f[0], f[1]);
        unpack2(acc[bi][1], f[2], f[3]);
        unpack2(acc[bi][2], f[4], f[5]);
        unpack2(acc[bi][3], f[6], f[7]);
        float* dst = out + ((size_t)(b0 + bi) * SEQ + t) * OUTD + o0;
        float4 v0, v1;
        v0.x = f[0] + byv[0]; v0.y = f[1] + byv[1];
        v0.z = f[2] + byv[2]; v0.w = f[3] + byv[3];
        v1.x = f[4] + byv[4]; v1.y = f[5] + byv[5];
        v1.z = f[6] + byv[6]; v1.w = f[7] + byv[7];
        *(float4*)(dst)     = v0;
        *(float4*)(dst + 4) = v1;
    }
}

// ---------------------------------------------------------------------------
// Launch. Inputs: X[i32 64x512], W_hh[f32 1024x1024], W_xh[f32 128x1024],
// W_hy[f32 1024x128], b_h[1024], b_y[128]. Output: f32 [64][512][128].
// ---------------------------------------------------------------------------
extern "C" void kernel_launch(void* const* d_in, const int* in_sizes, int n_in,
                              void* d_out, int out_size) {
    const int*   X    = (const int*)  d_in[0];
    const float* W_hh = (const float*)d_in[1];
    const float* W_xh = (const float*)d_in[2];
    const float* W_hy = (const float*)d_in[3];
    const float* b_h  = (const float*)d_in[4];
    const float* b_y  = (const float*)d_in[5];
    float* out = (float*)d_out;

    const int smem_rnn = (H * CPC + NSLOT * SLOT) * (int)sizeof(float)
                       + BPC * (int)sizeof(int);
    cudaFuncSetAttribute(rnn_recurrence_kernel,
                         cudaFuncAttributeMaxDynamicSharedMemorySize, smem_rnn);

    rnn_recurrence_kernel<<<G, NT, smem_rnn>>>(X, W_hh, W_xh, b_h);
    rnn_output_kernel<<<SEQ, 256>>>(W_hy, b_y, out);
}

// round 9
// speedup vs baseline: 1.3768x; 1.0788x over previous
#include <cuda_runtime.h>
#include <math.h>

// Problem constants
#define B    64
#define SEQ  512
#define H    1024
#define OUTD 128

// Recurrence config: R3-proven partition, 16 warps for latency hiding.
#define G    128           // persistent CTAs (<=148 SMs => co-resident, 1/SM)
#define CPC  8             // columns of W_hh per CTA (H / G)
#define NT   512           // 16 warps -> 4 per SMSP
#define NW   16
#define KC   (H / NW)      // 64 k per warp (lane k-parity -> 32 iters)
#define NSLOT (2 * NW)     // 32 partial slots (warp x k-parity)
#define SLOTSTRIDE 577     // 64*9 + 1 pad (float stores only — no alignment hazard)

static_assert(G * CPC == H, "partition");

typedef unsigned long long u64;

// Scratch (device globals: allocation-free rule). Zero-initialized at load.
__device__ float g_hs[(size_t)SEQ * H * B];  // hidden states [t][h][b]
__device__ float g_h0[H * B];                // initial h = 0 (never written)
__device__ unsigned g_arrive = 0;
__device__ volatile unsigned g_release = 0;

// ---------------------------------------------------------------------------
// Packed f32x2 helpers (Blackwell FFMA2)
// ---------------------------------------------------------------------------
__device__ __forceinline__ u64 dup2(float x) {
    u64 r; unsigned u = __float_as_uint(x);
    asm("mov.b64 %0, {%1, %2};" : "=l"(r) : "r"(u), "r"(u));
    return r;
}
__device__ __forceinline__ void ffma2(u64& d, u64 a, u64 b) {
    asm("fma.rn.f32x2 %0, %1, %2, %3;" : "=l"(d) : "l"(a), "l"(b), "l"(d));
}
__device__ __forceinline__ void unpack2(u64 v, float& x, float& y) {
    unsigned lo, hi;
    asm("mov.b64 {%0, %1}, %2;" : "=r"(lo), "=r"(hi) : "l"(v));
    x = __uint_as_float(lo); y = __uint_as_float(hi);
}

__device__ __forceinline__ float tanh_safe(float x) {
    float ax = fabsf(x);
    float e  = __expf(2.0f * ax);
    float r  = 1.0f - 2.0f / (e + 1.0f);
    return copysignf(r, x);
}

// ---------------------------------------------------------------------------
// Grid-wide barrier — exact R3/R4-proven version. Valid: 128 CTAs co-resident.
// Self-restoring across graph replays (g_arrive -> 0; g_release monotonic).
// ---------------------------------------------------------------------------
__device__ __forceinline__ void grid_sync() {
    __syncthreads();
    if (threadIdx.x == 0) {
        __threadfence();                       // publish this CTA's g_hs writes
        unsigned gen = g_release;
        if (atomicAdd(&g_arrive, 1u) == G - 1u) {
            g_arrive = 0;
            __threadfence();
            g_release = gen + 1u;              // sole writer for this generation
        } else {
            while (g_release == gen) { }
        }
        __threadfence();                       // acquire other CTAs' writes
    }
    __syncthreads();
}

// ---------------------------------------------------------------------------
// Persistent recurrence: h_t = tanh(h_{t-1} @ W_hh + W_xh[X[:,t]] + b_h)
// CTA c owns columns [c*8, c*8+8); W slice resident in smem all 512 steps.
// 16 warps split k (64 each); lane k-parity halves again. Lane tile 4b x 8j.
// ---------------------------------------------------------------------------
__global__ void __launch_bounds__(NT, 1)
rnn_recurrence_kernel(const int* __restrict__ X,
                      const float* __restrict__ W_hh,
                      const float* __restrict__ W_xh,
                      const float* __restrict__ b_h) {
    extern __shared__ float sm[];
    float* ws  = sm;                       // [H][CPC]    32 KB
    float* red = sm + H * CPC;             // [32][577]   ~72 KB

    const int tid = threadIdx.x;
    const int c0  = blockIdx.x * CPC;

    // One-time W_hh slice load (k-major rows of 8 columns)
    for (int i = tid; i < H * CPC; i += NT) {
        int k = i >> 3, j = i & 7;
        ws[i] = W_hh[(size_t)k * H + c0 + j];
    }

    const int w    = tid >> 5;
    const int lane = tid & 31;
    const int b4   = lane & 15;       // 4-batch group
    const int kpar = lane >> 4;       // k parity within warp
    const int bb0  = b4 * 4;
    const int slot = w * 2 + kpar;
    float* rstore  = red + slot * SLOTSTRIDE + bb0 * 9;

    // Reduce mapping: exactly 1 output per thread: j = tid>>6 (0..7), b = tid&63
    const int jr = tid >> 6;
    const int br = tid & 63;
    const float bh = b_h[c0 + jr];

    __syncthreads();

    for (int t = 0; t < SEQ; t++) {
        const float* hp = t ? (g_hs + (size_t)(t - 1) * H * B) : g_h0;

        // Early-issue token + W_xh gather (dependency-free; retires under GEMM)
        int   tk = X[br * SEQ + t];
        float wx = W_xh[(size_t)tk * H + c0 + jr];

        u64 acc[4][4];
        #pragma unroll
        for (int bi = 0; bi < 4; bi++)
            #pragma unroll
            for (int jp = 0; jp < 4; jp++) acc[bi][jp] = 0ull;

        const int kbeg = w * KC + kpar;
        const float* hb = hp + (size_t)kbeg * B + bb0;
        const float* wb = ws + kbeg * CPC;

        #pragma unroll 8
        for (int it = 0; it < KC / 2; it++) {
            float4 hv = *(const float4*)(hb + (size_t)it * 2 * B);
            ulonglong2 w0 = *(const ulonglong2*)(wb + it * 2 * CPC);      // (j0,j1),(j2,j3)
            ulonglong2 w1 = *(const ulonglong2*)(wb + it * 2 * CPC + 4);  // (j4,j5),(j6,j7)
            u64 h0 = dup2(hv.x), h1 = dup2(hv.y), h2 = dup2(hv.z), h3 = dup2(hv.w);
            ffma2(acc[0][0], h0, w0.x); ffma2(acc[0][1], h0, w0.y);
            ffma2(acc[0][2], h0, w1.x); ffma2(acc[0][3], h0, w1.y);
            ffma2(acc[1][0], h1, w0.x); ffma2(acc[1][1], h1, w0.y);
            ffma2(acc[1][2], h1, w1.x); ffma2(acc[1][3], h1, w1.y);
            ffma2(acc[2][0], h2, w0.x); ffma2(acc[2][1], h2, w0.y);
            ffma2(acc[2][2], h2, w1.x); ffma2(acc[2][3], h2, w1.y);
            ffma2(acc[3][0], h3, w0.x); ffma2(acc[3][1], h3, w0.y);
            ffma2(acc[3][2], h3, w1.x); ffma2(acc[3][3], h3, w1.y);
        }

        // Stash partials as plain floats (R3-proven pattern; no wide stores)
        #pragma unroll
        for (int bi = 0; bi < 4; bi++) {
            float f[8];
            unpack2(acc[bi][0], f[0], f[1]);
            unpack2(acc[bi][1], f[2], f[3]);
            unpack2(acc[bi][2], f[4], f[5]);
            unpack2(acc[bi][3], f[6], f[7]);
            #pragma unroll
            for (int j = 0; j < 8; j++) rstore[bi * 9 + j] = f[j];
        }
        __syncthreads();

        // Reduce 32 slots + input proj + bias + tanh; write h_t [h][b].
        {
            float s = 0.f;
            const float* rb = red + br * 9 + jr;
            #pragma unroll
            for (int sl = 0; sl < NSLOT; sl++)
                s += rb[sl * SLOTSTRIDE];
            float x = s + wx + bh;
            g_hs[(size_t)t * H * B + (size_t)(c0 + jr) * B + br] = tanh_safe(x);
        }

        grid_sync();
    }
}

// ---------------------------------------------------------------------------
// Output projection (unchanged, proven):
//   out[b][t][o] = sum_h hs[t][h][b] * W_hy[h][o] + b_y[o]
// ---------------------------------------------------------------------------
__global__ void __launch_bounds__(256)
rnn_output_kernel(const float* __restrict__ W_hy,
                  const float* __restrict__ b_y,
                  float* __restrict__ out) {
    __shared__ float hc[64 * 64];
    __shared__ float Wc[64 * OUTD];

    const int t   = blockIdx.x;
    const int tid = threadIdx.x;
    const int b0  = (tid & 15) * 4;
    const int o0  = (tid >> 4) * 8;

    u64 acc[4][4];
    #pragma unroll
    for (int bi = 0; bi < 4; bi++)
        #pragma unroll
        for (int op = 0; op < 4; op++) acc[bi][op] = 0ull;

    const float* hsrc = g_hs + (size_t)t * H * B;

    for (int k0 = 0; k0 < H; k0 += 64) {
        const float4* hsv = (const float4*)(hsrc + (size_t)k0 * B);
        float4* hcv = (float4*)hc;
        #pragma unroll
        for (int i = 0; i < 4; i++) hcv[tid + i * 256] = hsv[tid + i * 256];

        const float4* wsv = (const float4*)(W_hy + (size_t)k0 * OUTD);
        float4* wcv = (float4*)Wc;
        #pragma unroll
        for (int i = 0; i < 8; i++) wcv[tid + i * 256] = wsv[tid + i * 256];

        __syncthreads();

        #pragma unroll 4
        for (int k = 0; k < 64; k++) {
            float4 hv = *(const float4*)(hc + k * 64 + b0);
            ulonglong2 wq0 = *(const ulonglong2*)(Wc + k * OUTD + o0);
            ulonglong2 wq1 = *(const ulonglong2*)(Wc + k * OUTD + o0 + 4);
            u64 h0 = dup2(hv.x), h1 = dup2(hv.y), h2 = dup2(hv.z), h3 = dup2(hv.w);
            ffma2(acc[0][0], h0, wq0.x); ffma2(acc[0][1], h0, wq0.y);
            ffma2(acc[0][2], h0, wq1.x); ffma2(acc[0][3], h0, wq1.y);
            ffma2(acc[1][0], h1, wq0.x); ffma2(acc[1][1], h1, wq0.y);
            ffma2(acc[1][2], h1, wq1.x); ffma2(acc[1][3], h1, wq1.y);
            ffma2(acc[2][0], h2, wq0.x); ffma2(acc[2][1], h2, wq0.y);
            ffma2(acc[2][2], h2, wq1.x); ffma2(acc[2][3], h2, wq1.y);
            ffma2(acc[3][0], h3, wq0.x); ffma2(acc[3][1], h3, wq0.y);
            ffma2(acc[3][2], h3, wq1.x); ffma2(acc[3][3], h3, wq1.y);
        }
        __syncthreads();
    }

    float byv[8];
    #pragma unroll
    for (int oi = 0; oi < 8; oi++) byv[oi] = b_y[o0 + oi];

    #pragma unroll
    for (int bi = 0; bi < 4; bi++) {
        float f[8];
        unpack2(acc[bi][0], f[0], f[1]);
        unpack2(acc[bi][1], f[2], f[3]);
        unpack2(acc[bi][2], f[4], f[5]);
        unpack2(acc[bi][3], f[6], f[7]);
        float* dst = out + ((size_t)(b0 + bi) * SEQ + t) * OUTD + o0;
        float4 v0, v1;
        v0.x = f[0] + byv[0]; v0.y = f[1] + byv[1];
        v0.z = f[2] + byv[2]; v0.w = f[3] + byv[3];
        v1.x = f[4] + byv[4]; v1.y = f[5] + byv[5];
        v1.z = f[6] + byv[6]; v1.w = f[7] + byv[7];
        *(float4*)(dst)     = v0;
        *(float4*)(dst + 4) = v1;
    }
}

// ---------------------------------------------------------------------------
// Launch. Inputs: X[i32 64x512], W_hh[f32 1024x1024], W_xh[f32 128x1024],
// W_hy[f32 1024x128], b_h[1024], b_y[128]. Output: f32 [64][512][128].
// ---------------------------------------------------------------------------
extern "C" void kernel_launch(void* const* d_in, const int* in_sizes, int n_in,
                              void* d_out, int out_size) {
    const int*   X    = (const int*)  d_in[0];
    const float* W_hh = (const float*)d_in[1];
    const float* W_xh = (const float*)d_in[2];
    const float* W_hy = (const float*)d_in[3];
    const float* b_h  = (const float*)d_in[4];
    const float* b_y  = (const float*)d_in[5];
    float* out = (float*)d_out;

    const int smem_rnn = (H * CPC + NSLOT * SLOTSTRIDE) * (int)sizeof(float);
    cudaFuncSetAttribute(rnn_recurrence_kernel,
                         cudaFuncAttributeMaxDynamicSharedMemorySize, smem_rnn);

    rnn_recurrence_kernel<<<G, NT, smem_rnn>>>(X, W_hh, W_xh, b_h);
    rnn_output_kernel<<<SEQ, 256>>>(W_hy, b_y, out);
}